// round 2
// baseline (speedup 1.0000x reference)
#include <cuda_runtime.h>
#include <math.h>
#include <stdint.h>

// ---------------- problem constants ----------------
#define VOCAB   8192
#define DIM     512
#define M_ROWS  32768          // 8*4096
#define MOM     0.995f
// output packing (flat f32, tuple order): x_q | loss | perplexity | new_dict | new_counts
#define OFF_XQ   0ull
#define OFF_LOSS 16777216ull
#define OFF_PERP 16777217ull
#define OFF_DICT 16777218ull
#define OFF_CNT  20971522ull   // OFF_DICT + VOCAB*DIM

// ---------------- device scratch (no allocations allowed) ----------------
__device__ float               g_e[VOCAB * DIM];   // codewords e = dict / counts
__device__ float               g_h[VOCAB];         // 0.5*||e_k||^2
__device__ unsigned long long  g_best[M_ROWS];     // packed (score_bits<<32 | (8191-k))
__device__ float               g_cnt[VOCAB];       // histogram
__device__ double              g_loss;             // sum (e[id]-x)^2

// ---------------- kernel A: codewords + half squared norms ----------------
__global__ void compute_codewords(const float* __restrict__ dict,
                                  const float* __restrict__ counts) {
    int k = blockIdx.x;              // one block per codeword, 128 threads
    int t = threadIdx.x;
    float inv = 1.0f / counts[k];
    const float4* src = (const float4*)(dict + (size_t)k * DIM);
    float4*       dst = (float4*)(g_e + (size_t)k * DIM);
    float4 v = src[t];
    v.x *= inv; v.y *= inv; v.z *= inv; v.w *= inv;
    dst[t] = v;
    float s = v.x * v.x + v.y * v.y + v.z * v.z + v.w * v.w;
    #pragma unroll
    for (int o = 16; o; o >>= 1) s += __shfl_xor_sync(0xffffffffu, s, o);
    __shared__ float ws[4];
    if ((t & 31) == 0) ws[t >> 5] = s;
    __syncthreads();
    if (t == 0) g_h[k] = 0.5f * (ws[0] + ws[1] + ws[2] + ws[3]);
}

// ---------------- kernel B: init scratch + new_dict = 0.995*dict ----------------
__global__ void init_kernel(const float* __restrict__ dict, float* __restrict__ out) {
    size_t i = (size_t)blockIdx.x * blockDim.x + threadIdx.x;
    size_t stride = (size_t)gridDim.x * blockDim.x;
    const size_t nd2 = (size_t)VOCAB * DIM / 2;   // float2 elements
    float2* od = (float2*)(out + OFF_DICT);       // OFF_DICT is even -> 8B aligned
    const float2* dd = (const float2*)dict;
    for (size_t j = i; j < nd2; j += stride) {
        float2 d = dd[j];
        d.x *= MOM; d.y *= MOM;
        od[j] = d;
    }
    for (size_t j = i; j < M_ROWS; j += stride) g_best[j] = 0ull;
    for (size_t j = i; j < VOCAB;  j += stride) g_cnt[j] = 0.0f;
    if (i == 0) g_loss = 0.0;
}

// ---------------- kernel C: SGEMM (X @ E^T) fused with streaming argmax ----------------
// score[m,k] = x_m . e_k - 0.5*||e_k||^2 ; argmax_k == argmin of squared distance.
// 128x128 block tile, 8x8 per-thread microtile, K(C)-chunk = 8, register prefetch.
__global__ void __launch_bounds__(256, 2)
gemm_argmax(const float* __restrict__ X) {
    __shared__ float As[8][128];
    __shared__ float Bs[8][128];
    const int bx = blockIdx.x;          // 64 codeword tiles
    const int by = blockIdx.y;          // 256 row tiles
    const int tid = threadIdx.x;
    const int tx = tid & 15;
    const int ty = tid >> 4;
    const int lrow = tid >> 1;          // 0..127
    const int lk   = (tid & 1) * 4;     // 0 or 4

    const float* Xp = X   + ((size_t)by * 128 + lrow) * DIM + lk;
    const float* Ep = g_e + ((size_t)bx * 128 + lrow) * DIM + lk;

    float acc[8][8];
    #pragma unroll
    for (int i = 0; i < 8; i++)
        #pragma unroll
        for (int j = 0; j < 8; j++) acc[i][j] = 0.0f;

    float4 pa = *(const float4*)Xp;
    float4 pb = *(const float4*)Ep;

    for (int c0 = 0; c0 < DIM; c0 += 8) {
        As[lk + 0][lrow] = pa.x; As[lk + 1][lrow] = pa.y;
        As[lk + 2][lrow] = pa.z; As[lk + 3][lrow] = pa.w;
        Bs[lk + 0][lrow] = pb.x; Bs[lk + 1][lrow] = pb.y;
        Bs[lk + 2][lrow] = pb.z; Bs[lk + 3][lrow] = pb.w;
        __syncthreads();
        if (c0 + 8 < DIM) {                 // prefetch next chunk into registers
            pa = *(const float4*)(Xp + c0 + 8);
            pb = *(const float4*)(Ep + c0 + 8);
        }
        #pragma unroll
        for (int k = 0; k < 8; k++) {
            float ra[8], rb[8];
            *(float4*)&ra[0] = *(const float4*)&As[k][ty * 4];
            *(float4*)&ra[4] = *(const float4*)&As[k][64 + ty * 4];
            *(float4*)&rb[0] = *(const float4*)&Bs[k][tx * 4];
            *(float4*)&rb[4] = *(const float4*)&Bs[k][64 + tx * 4];
            #pragma unroll
            for (int i = 0; i < 8; i++)
                #pragma unroll
                for (int j = 0; j < 8; j++)
                    acc[i][j] = fmaf(ra[i], rb[j], acc[i][j]);
        }
        __syncthreads();
    }

    // epilogue: per-row argmax over this block's 128 codewords, merge via atomicMax
    float hv[8];
    int   cols[8];
    #pragma unroll
    for (int j = 0; j < 8; j++) {
        int c = bx * 128 + ((j < 4) ? (tx * 4 + j) : (64 + tx * 4 + (j - 4)));
        cols[j] = c;
        hv[j] = g_h[c];
    }
    #pragma unroll
    for (int i = 0; i < 8; i++) {
        int row = by * 128 + ((i < 4) ? (ty * 4 + i) : (64 + ty * 4 + (i - 4)));
        float bs = -1e30f; int bc = 0;
        #pragma unroll
        for (int j = 0; j < 8; j++) {
            float s = acc[i][j] - hv[j];
            if (s > bs || (s == bs && cols[j] < bc)) { bs = s; bc = cols[j]; }
        }
        unsigned int ub = __float_as_uint(bs);
        ub = (ub & 0x80000000u) ? ~ub : (ub | 0x80000000u);  // order-preserving map
        unsigned long long key =
            ((unsigned long long)ub << 32) | (unsigned int)(VOCAB - 1 - bc);
        // reduce across the 16 lanes (same ty) owning this row's 128 columns
        #pragma unroll
        for (int o = 8; o; o >>= 1) {
            unsigned long long other = __shfl_xor_sync(0xffffffffu, key, o);
            if (other > key) key = other;
        }
        if (tx == 0) atomicMax(&g_best[row], key);
    }
}

// ---------------- kernel D: gather x_q, loss, histogram, scatter x_sum ----------------
__global__ void scatter_kernel(const float* __restrict__ X, float* __restrict__ out) {
    int gw   = ((int)blockIdx.x * blockDim.x + threadIdx.x) >> 5;  // global warp = row
    int lane = threadIdx.x & 31;
    __shared__ double lred[8];
    double lsum = 0.0;
    if (gw < M_ROWS) {
        unsigned long long key = g_best[gw];
        int k = VOCAB - 1 - (int)(key & 0xffffffffu);
        const float4* e4 = (const float4*)(g_e + (size_t)k * DIM);
        const float4* x4 = (const float4*)(X + (size_t)gw * DIM);
        float4*       q4 = (float4*)(out + (size_t)gw * DIM);
        float* nd = out + OFF_DICT + (size_t)k * DIM;
        float fs = 0.0f;
        #pragma unroll
        for (int c = lane; c < DIM / 4; c += 32) {
            float4 e = e4[c], x = x4[c];
            q4[c] = e;                       // x_q = e[id]
            float dx = e.x - x.x, dy = e.y - x.y, dz = e.z - x.z, dw = e.w - x.w;
            fs += dx * dx + dy * dy + dz * dz + dw * dw;
            atomicAdd(nd + c * 4 + 0, x.x);
            atomicAdd(nd + c * 4 + 1, x.y);
            atomicAdd(nd + c * 4 + 2, x.z);
            atomicAdd(nd + c * 4 + 3, x.w);
        }
        #pragma unroll
        for (int o = 16; o; o >>= 1) fs += __shfl_xor_sync(0xffffffffu, fs, o);
        if (lane == 0) {
            atomicAdd(&g_cnt[k], 1.0f);
            lsum = (double)fs;
        }
    }
    int wid = threadIdx.x >> 5;
    if (lane == 0) lred[wid] = lsum;
    __syncthreads();
    if (threadIdx.x == 0) {
        double t = 0.0;
        for (int i = 0; i < 8; i++) t += lred[i];
        atomicAdd(&g_loss, t);
    }
}

// ---------------- kernel E: new_counts, loss, perplexity ----------------
__global__ void finalize_kernel(const float* __restrict__ counts, float* __restrict__ out) {
    __shared__ double red[32];
    __shared__ double s_total;
    int tid = threadIdx.x;   // 1024 threads
    double s = 0.0;
    for (int k = tid; k < VOCAB; k += 1024) {
        float nc = counts[k] * MOM + g_cnt[k];
        out[OFF_CNT + k] = nc;
        s += (double)nc;
    }
    #pragma unroll
    for (int o = 16; o; o >>= 1) s += __shfl_xor_sync(0xffffffffu, s, o);
    if ((tid & 31) == 0) red[tid >> 5] = s;
    __syncthreads();
    if (tid < 32) {
        double t = red[tid];
        #pragma unroll
        for (int o = 16; o; o >>= 1) t += __shfl_xor_sync(0xffffffffu, t, o);
        if (tid == 0) s_total = t;
    }
    __syncthreads();
    double total = s_total;
    double h = 0.0;
    for (int k = tid; k < VOCAB; k += 1024) {
        double p = (double)out[OFF_CNT + k] / total;
        h += p * log(p + 1e-10);
    }
    #pragma unroll
    for (int o = 16; o; o >>= 1) h += __shfl_xor_sync(0xffffffffu, h, o);
    if ((tid & 31) == 0) red[tid >> 5] = h;
    __syncthreads();
    if (tid == 0) {
        double t = 0.0;
        for (int i = 0; i < 32; i++) t += red[i];
        out[OFF_PERP] = (float)exp(-t);
        out[OFF_LOSS] = (float)(0.25 * g_loss / 16777216.0);
    }
}

// ---------------- launch ----------------
extern "C" void kernel_launch(void* const* d_in, const int* in_sizes, int n_in,
                              void* d_out, int out_size) {
    (void)in_sizes; (void)n_in; (void)out_size;
    const float* X      = (const float*)d_in[0];
    const float* dict   = (const float*)d_in[1];
    const float* counts = (const float*)d_in[2];
    float* out = (float*)d_out;

    compute_codewords<<<VOCAB, 128>>>(dict, counts);
    init_kernel<<<2048, 256>>>(dict, out);
    dim3 grid(VOCAB / 128, M_ROWS / 128);   // (64, 256)
    gemm_argmax<<<grid, 256>>>(X);
    scatter_kernel<<<M_ROWS * 32 / 256, 256>>>(X, out);
    finalize_kernel<<<1, 1024>>>(counts, out);
}

// round 4
// speedup vs baseline: 1.1644x; 1.1644x over previous
#include <cuda_runtime.h>
#include <math.h>
#include <stdint.h>

// ---------------- problem constants ----------------
#define VOCAB   8192
#define DIM     512
#define M_ROWS  32768          // 8*4096
#define MOM     0.995f
// output packing (flat f32, tuple order): x_q | loss | perplexity | new_dict | new_counts
#define OFF_LOSS 16777216ull
#define OFF_PERP 16777217ull
#define OFF_DICT 16777218ull
#define OFF_CNT  20971522ull   // OFF_DICT + VOCAB*DIM

// ---------------- GEMM tiling ----------------
#define TM      128
#define TN      128
#define KC      16
#define NCHUNK  (DIM / KC)     // 32
#define ACHUNK  (TM * KC)      // 2048 floats per (tile, chunk) packed block
#define STAGE_BYTES 32768      // Ahi|Alo|Bhi|Blo, 8KB each
#define SM_H     131072        // after 4 stages
#define SM_BEST  131584
#define SM_TOTAL 132608

// ---------------- device scratch (static; no allocations) ----------------
__device__ float               g_e[VOCAB * DIM];
__device__ float               g_h[VOCAB];
__device__ unsigned long long  g_best[M_ROWS];
__device__ float               g_cnt[VOCAB];
__device__ double              g_loss;
// fragment-packed tf32 limbs
__device__ float               g_xhi[M_ROWS * DIM];
__device__ float               g_xlo[M_ROWS * DIM];
__device__ float               g_ehi[VOCAB * DIM];
__device__ float               g_elo[VOCAB * DIM];

// ---------------- helpers ----------------
__device__ __forceinline__ float tf32r(float x) {
    uint32_t b;
    asm("cvt.rna.tf32.f32 %0, %1;" : "=r"(b) : "f"(x));
    return __uint_as_float(b);
}
__device__ __forceinline__ uint32_t smem_u32(const void* p) {
    uint32_t a;
    asm("{ .reg .u64 t; cvta.to.shared.u64 t, %1; cvt.u32.u64 %0, t; }" : "=r"(a) : "l"(p));
    return a;
}
__device__ __forceinline__ void cp16(uint32_t dst, const void* src) {
    asm volatile("cp.async.ca.shared.global [%0], [%1], 16;" :: "r"(dst), "l"(src));
}
#define CP_COMMIT() asm volatile("cp.async.commit_group;")
#define CP_WAIT(n)  asm volatile("cp.async.wait_group %0;" :: "n"(n))

#define MMA(d, a0, a1, a2, a3, b0, b1)                                        \
    asm volatile(                                                             \
        "mma.sync.aligned.m16n8k8.row.col.f32.tf32.tf32.f32 "                 \
        "{%0,%1,%2,%3}, {%4,%5,%6,%7}, {%8,%9}, {%0,%1,%2,%3};"               \
        : "+f"(d[0]), "+f"(d[1]), "+f"(d[2]), "+f"(d[3])                      \
        : "r"(a0), "r"(a1), "r"(a2), "r"(a3), "r"(b0), "r"(b1))

// ---------------- kernel A: codewords + half squared norms ----------------
__global__ void compute_codewords(const float* __restrict__ dict,
                                  const float* __restrict__ counts) {
    int k = blockIdx.x;
    int t = threadIdx.x;
    float inv = 1.0f / counts[k];
    const float4* src = (const float4*)(dict + (size_t)k * DIM);
    float4*       dst = (float4*)(g_e + (size_t)k * DIM);
    float4 v = src[t];
    v.x *= inv; v.y *= inv; v.z *= inv; v.w *= inv;
    dst[t] = v;
    float s = v.x * v.x + v.y * v.y + v.z * v.z + v.w * v.w;
    #pragma unroll
    for (int o = 16; o; o >>= 1) s += __shfl_xor_sync(0xffffffffu, s, o);
    __shared__ float ws[4];
    if ((t & 31) == 0) ws[t >> 5] = s;
    __syncthreads();
    if (t == 0) g_h[k] = 0.5f * (ws[0] + ws[1] + ws[2] + ws[3]);
}

// ---------------- split X into fragment-packed tf32 hi/lo ----------------
// packed float index within (mt, c) chunk-tile: q = msub*256 + ks*128 + lane*4 + j
// A-frag element (j): j0=(r,c), j1=(r+8,c), j2=(r,c+4), j3=(r+8,c+4); r=lane/4, c=lane%4
__global__ void split_x(const float* __restrict__ X) {
    int o4 = blockIdx.x * 256 + threadIdx.x;     // float4 index, 4194304 total
    int o  = o4 * 4;
    int t    = (o >> 2)  & 31;
    int ks   = (o >> 7)  & 1;
    int msub = (o >> 8)  & 7;
    int c    = (o >> 11) & 31;
    int mt   =  o >> 16;
    int m = mt * 128 + msub * 16 + (t >> 2);
    int k = c * 16 + ks * 8 + (t & 3);
    const float* xp = X + (size_t)m * DIM + k;
    float x00 = xp[0], x01 = xp[4];
    float x10 = xp[8 * DIM], x11 = xp[8 * DIM + 4];
    float4 h, l;
    h.x = tf32r(x00); l.x = tf32r(x00 - h.x);
    h.y = tf32r(x10); l.y = tf32r(x10 - h.y);
    h.z = tf32r(x01); l.z = tf32r(x01 - h.z);
    h.w = tf32r(x11); l.w = tf32r(x11 - h.w);
    ((float4*)g_xhi)[o4] = h;
    ((float4*)g_xlo)[o4] = l;
}

// packed B index within (nt, c): q = nsub*128 + ks*64 + lane*2 + j
// B-frag element (j): j0=(k=lane%4, n=lane/4), j1=(k=lane%4+4, n=lane/4)
__global__ void split_e() {
    int o2 = blockIdx.x * 256 + threadIdx.x;     // float2 index, 2097152 total
    int o  = o2 * 2;
    int t    = (o >> 1)  & 31;
    int ks   = (o >> 6)  & 1;
    int nsub = (o >> 7)  & 15;
    int c    = (o >> 11) & 31;
    int nt   =  o >> 16;
    int n = nt * 128 + nsub * 8 + (t >> 2);
    int k = c * 16 + ks * 8 + (t & 3);
    const float* ep = g_e + (size_t)n * DIM + k;
    float e0 = ep[0], e1 = ep[4];
    float2 h, l;
    h.x = tf32r(e0); l.x = tf32r(e0 - h.x);
    h.y = tf32r(e1); l.y = tf32r(e1 - h.y);
    ((float2*)g_ehi)[o2] = h;
    ((float2*)g_elo)[o2] = l;
}

// ---------------- kernel B: init scratch + new_dict = 0.995*dict ----------------
__global__ void init_kernel(const float* __restrict__ dict, float* __restrict__ out) {
    size_t i = (size_t)blockIdx.x * blockDim.x + threadIdx.x;
    size_t stride = (size_t)gridDim.x * blockDim.x;
    const size_t nd2 = (size_t)VOCAB * DIM / 2;
    float2* od = (float2*)(out + OFF_DICT);
    const float2* dd = (const float2*)dict;
    for (size_t j = i; j < nd2; j += stride) {
        float2 d = dd[j];
        d.x *= MOM; d.y *= MOM;
        od[j] = d;
    }
    for (size_t j = i; j < M_ROWS; j += stride) g_best[j] = 0ull;
    for (size_t j = i; j < VOCAB;  j += stride) g_cnt[j] = 0.0f;
    if (i == 0) g_loss = 0.0;
}

// ---------------- kernel C: 3xTF32 mma.sync GEMM + fused argmax ----------------
__global__ void __launch_bounds__(256, 1)
gemm_argmax_mma() {
    extern __shared__ char sm[];
    uint32_t smb = smem_u32(sm);
    float* h_s = (float*)(sm + SM_H);
    unsigned long long* sbest = (unsigned long long*)(sm + SM_BEST);
    const int tid = threadIdx.x, lane = tid & 31, w = tid >> 5;
    const int wm = w >> 2, wn = w & 3;
    const int nt = blockIdx.x, mt = blockIdx.y;

    for (int i = tid; i < TN; i += 256) h_s[i] = g_h[nt * TN + i];
    if (tid < TM) sbest[tid] = 0ull;

    const float* gah = g_xhi + (size_t)mt * NCHUNK * ACHUNK;
    const float* gal = g_xlo + (size_t)mt * NCHUNK * ACHUNK;
    const float* gbh = g_ehi + (size_t)nt * NCHUNK * ACHUNK;
    const float* gbl = g_elo + (size_t)nt * NCHUNK * ACHUNK;

    float acc[4][4][4];
    #pragma unroll
    for (int i = 0; i < 4; i++)
        #pragma unroll
        for (int j = 0; j < 4; j++)
            #pragma unroll
            for (int r = 0; r < 4; r++) acc[i][j][r] = 0.0f;

    auto issue = [&](int c) {
        uint32_t sb = smb + (uint32_t)(c & 3) * STAGE_BYTES;
        int co = c * ACHUNK;
        cp16(sb +         tid * 16, gah + co + tid * 4);
        cp16(sb +  4096 + tid * 16, gah + co + 1024 + tid * 4);
        cp16(sb +  8192 + tid * 16, gal + co + tid * 4);
        cp16(sb + 12288 + tid * 16, gal + co + 1024 + tid * 4);
        cp16(sb + 16384 + tid * 16, gbh + co + tid * 4);
        cp16(sb + 20480 + tid * 16, gbh + co + 1024 + tid * 4);
        cp16(sb + 24576 + tid * 16, gbl + co + tid * 4);
        cp16(sb + 28672 + tid * 16, gbl + co + 1024 + tid * 4);
        CP_COMMIT();
    };

    issue(0); issue(1); issue(2);

    for (int c = 0; c < NCHUNK; c++) {
        if (c + 3 < NCHUNK) issue(c + 3);
        int rem = NCHUNK - 1 - c;               // groups newer than chunk c
        if      (rem >= 3) CP_WAIT(3);
        else if (rem == 2) CP_WAIT(2);
        else if (rem == 1) CP_WAIT(1);
        else               CP_WAIT(0);
        __syncthreads();

        int sbase = (c & 3) * STAGE_BYTES;
        #pragma unroll
        for (int ks = 0; ks < 2; ks++) {
            uint32_t ah[4][4], al[4][4], bh[4][2], bl[4][2];
            #pragma unroll
            for (int i = 0; i < 4; i++) {
                int ao = sbase + ((wm * 4 + i) * 2 + ks) * 512 + lane * 16;
                float4 vh = *(const float4*)(sm + ao);
                float4 vl = *(const float4*)(sm + 8192 + ao);
                ah[i][0] = __float_as_uint(vh.x); ah[i][1] = __float_as_uint(vh.y);
                ah[i][2] = __float_as_uint(vh.z); ah[i][3] = __float_as_uint(vh.w);
                al[i][0] = __float_as_uint(vl.x); al[i][1] = __float_as_uint(vl.y);
                al[i][2] = __float_as_uint(vl.z); al[i][3] = __float_as_uint(vl.w);
            }
            #pragma unroll
            for (int jn = 0; jn < 4; jn++) {
                int bo = sbase + 16384 + ((wn * 4 + jn) * 2 + ks) * 256 + lane * 8;
                float2 vh = *(const float2*)(sm + bo);
                float2 vl = *(const float2*)(sm + 8192 + bo);
                bh[jn][0] = __float_as_uint(vh.x); bh[jn][1] = __float_as_uint(vh.y);
                bl[jn][0] = __float_as_uint(vl.x); bl[jn][1] = __float_as_uint(vl.y);
            }
            #pragma unroll
            for (int i = 0; i < 4; i++)
                #pragma unroll
                for (int jn = 0; jn < 4; jn++) {
                    MMA(acc[i][jn], ah[i][0], ah[i][1], ah[i][2], ah[i][3],
                        bh[jn][0], bh[jn][1]);
                    MMA(acc[i][jn], ah[i][0], ah[i][1], ah[i][2], ah[i][3],
                        bl[jn][0], bl[jn][1]);
                    MMA(acc[i][jn], al[i][0], al[i][1], al[i][2], al[i][3],
                        bh[jn][0], bh[jn][1]);
                }
        }
        __syncthreads();
    }

    // ---- epilogue: streaming argmax over this 128x128 tile ----
    #pragma unroll
    for (int i = 0; i < 4; i++) {
        #pragma unroll
        for (int half = 0; half < 2; half++) {
            int row = wm * 64 + i * 16 + (lane >> 2) + half * 8;
            float bs = -1e30f;
            int   bc = 0;
            #pragma unroll
            for (int jn = 0; jn < 4; jn++) {
                #pragma unroll
                for (int p = 0; p < 2; p++) {
                    int coll = wn * 32 + jn * 8 + (lane & 3) * 2 + p;
                    float s = acc[i][jn][half * 2 + p] - h_s[coll];
                    int col = nt * TN + coll;
                    if (s > bs || (s == bs && col < bc)) { bs = s; bc = col; }
                }
            }
            unsigned int ub = __float_as_uint(bs);
            ub = (ub & 0x80000000u) ? ~ub : (ub | 0x80000000u);
            unsigned long long key =
                ((unsigned long long)ub << 32) | (unsigned int)(VOCAB - 1 - bc);
            #pragma unroll
            for (int off = 1; off < 4; off <<= 1) {
                unsigned long long other = __shfl_xor_sync(0xffffffffu, key, off);
                if (other > key) key = other;
            }
            if ((lane & 3) == 0) atomicMax(&sbest[row], key);
        }
    }
    __syncthreads();
    if (tid < TM) atomicMax(&g_best[(size_t)mt * TM + tid], sbest[tid]);
}

// ---------------- kernel D: gather x_q, loss, histogram, scatter x_sum ----------------
__global__ void scatter_kernel(const float* __restrict__ X, float* __restrict__ out) {
    int gw   = ((int)blockIdx.x * blockDim.x + threadIdx.x) >> 5;  // row
    int lane = threadIdx.x & 31;
    __shared__ double lred[8];
    double lsum = 0.0;
    if (gw < M_ROWS) {
        unsigned long long key = g_best[gw];
        int k = VOCAB - 1 - (int)(key & 0xffffffffu);
        const float4* e4 = (const float4*)(g_e + (size_t)k * DIM);
        const float4* x4 = (const float4*)(X + (size_t)gw * DIM);
        float4*       q4 = (float4*)(out + (size_t)gw * DIM);
        float* nd = out + OFF_DICT + (size_t)k * DIM;
        float fs = 0.0f;
        #pragma unroll
        for (int c = lane; c < DIM / 4; c += 32) {
            float4 e = e4[c], x = x4[c];
            q4[c] = e;
            float dx = e.x - x.x, dy = e.y - x.y, dz = e.z - x.z, dw = e.w - x.w;
            fs += dx * dx + dy * dy + dz * dz + dw * dw;
            atomicAdd(nd + c * 4 + 0, x.x);
            atomicAdd(nd + c * 4 + 1, x.y);
            atomicAdd(nd + c * 4 + 2, x.z);
            atomicAdd(nd + c * 4 + 3, x.w);
        }
        #pragma unroll
        for (int o = 16; o; o >>= 1) fs += __shfl_xor_sync(0xffffffffu, fs, o);
        if (lane == 0) {
            atomicAdd(&g_cnt[k], 1.0f);
            lsum = (double)fs;
        }
    }
    int wid = threadIdx.x >> 5;
    if (lane == 0) lred[wid] = lsum;
    __syncthreads();
    if (threadIdx.x == 0) {
        double t = 0.0;
        for (int i = 0; i < 8; i++) t += lred[i];
        atomicAdd(&g_loss, t);
    }
}

// ---------------- kernel E: new_counts, loss, perplexity ----------------
__global__ void finalize_kernel(const float* __restrict__ counts, float* __restrict__ out) {
    __shared__ double red[32];
    __shared__ double s_total;
    int tid = threadIdx.x;
    double s = 0.0;
    for (int k = tid; k < VOCAB; k += 1024) {
        float nc = counts[k] * MOM + g_cnt[k];
        out[OFF_CNT + k] = nc;
        s += (double)nc;
    }
    #pragma unroll
    for (int o = 16; o; o >>= 1) s += __shfl_xor_sync(0xffffffffu, s, o);
    if ((tid & 31) == 0) red[tid >> 5] = s;
    __syncthreads();
    if (tid < 32) {
        double t = red[tid];
        #pragma unroll
        for (int o = 16; o; o >>= 1) t += __shfl_xor_sync(0xffffffffu, t, o);
        if (tid == 0) s_total = t;
    }
    __syncthreads();
    double total = s_total;
    double h = 0.0;
    for (int k = tid; k < VOCAB; k += 1024) {
        double p = (double)out[OFF_CNT + k] / total;
        h += p * log(p + 1e-10);
    }
    #pragma unroll
    for (int o = 16; o; o >>= 1) h += __shfl_xor_sync(0xffffffffu, h, o);
    if ((tid & 31) == 0) red[tid >> 5] = h;
    __syncthreads();
    if (tid == 0) {
        double t = 0.0;
        for (int i = 0; i < 32; i++) t += red[i];
        out[OFF_PERP] = (float)exp(-t);
        out[OFF_LOSS] = (float)(0.25 * g_loss / 16777216.0);
    }
}

// ---------------- launch ----------------
extern "C" void kernel_launch(void* const* d_in, const int* in_sizes, int n_in,
                              void* d_out, int out_size) {
    (void)in_sizes; (void)n_in; (void)out_size;
    const float* X      = (const float*)d_in[0];
    const float* dict   = (const float*)d_in[1];
    const float* counts = (const float*)d_in[2];
    float* out = (float*)d_out;

    cudaFuncSetAttribute(gemm_argmax_mma,
                         cudaFuncAttributeMaxDynamicSharedMemorySize, SM_TOTAL);

    compute_codewords<<<VOCAB, 128>>>(dict, counts);
    split_e<<<8192, 256>>>();
    split_x<<<16384, 256>>>(X);
    init_kernel<<<2048, 256>>>(dict, out);
    dim3 grid(VOCAB / TN, M_ROWS / TM);   // (64, 256)
    gemm_argmax_mma<<<grid, 256, SM_TOTAL>>>();
    scatter_kernel<<<M_ROWS * 32 / 256, 256>>>(X, out);
    finalize_kernel<<<1, 1024>>>(counts, out);
}

// round 5
// speedup vs baseline: 2.1664x; 1.8605x over previous
#include <cuda_runtime.h>
#include <cuda_fp16.h>
#include <math.h>
#include <stdint.h>

// ---------------- problem constants ----------------
#define VOCAB   8192
#define DIM     512
#define M_ROWS  32768          // 8*4096
#define MOM     0.995f
// output packing (flat f32, tuple order): x_q | loss | perplexity | new_dict | new_counts
#define OFF_LOSS 16777216ull
#define OFF_PERP 16777217ull
#define OFF_DICT 16777218ull
#define OFF_CNT  20971522ull   // OFF_DICT + VOCAB*DIM

// ---------------- GEMM tiling ----------------
#define TM      128
#define TN      256
#define KC      16
#define NCHUNK  (DIM / KC)     // 32
#define XSCALE  16.0f
#define ESCALE  1024.0f
#define HSCALE  16384.0f       // XSCALE*ESCALE
// A chunk: 8 msub x 2 limb x 32 lane x 16B = 8KB ; B chunk: 32 nsub x 2 limb x 32 lane x 8B = 16KB
#define STAGE_BYTES 24576
#define SM_H     98304         // after 4 stages
#define SM_BEST  99328
#define SM_TOTAL 100352

// ---------------- device scratch (static; no allocations) ----------------
__device__ float               g_e[VOCAB * DIM];
__device__ float               g_h[VOCAB];
__device__ unsigned long long  g_best[M_ROWS];
__device__ float               g_cnt[VOCAB];
__device__ double              g_loss;
// fragment-packed fp16 limb operands (hi/lo interleaved per fragment block)
__device__ uint32_t            g_xp[M_ROWS * DIM / 2 * 2];   // 64MB
__device__ uint32_t            g_ep[VOCAB  * DIM / 2 * 2];   // 16MB

// ---------------- helpers ----------------
__device__ __forceinline__ uint32_t smem_u32(const void* p) {
    uint32_t a;
    asm("{ .reg .u64 t; cvta.to.shared.u64 t, %1; cvt.u32.u64 %0, t; }" : "=r"(a) : "l"(p));
    return a;
}
__device__ __forceinline__ void cp16(uint32_t dst, const void* src) {
    asm volatile("cp.async.ca.shared.global [%0], [%1], 16;" :: "r"(dst), "l"(src));
}
#define CP_COMMIT() asm volatile("cp.async.commit_group;")
#define CP_WAIT(n)  asm volatile("cp.async.wait_group %0;" :: "n"(n))

#define MMA16(d, a0, a1, a2, a3, b0, b1)                                      \
    asm volatile(                                                             \
        "mma.sync.aligned.m16n8k16.row.col.f32.f16.f16.f32 "                  \
        "{%0,%1,%2,%3}, {%4,%5,%6,%7}, {%8,%9}, {%0,%1,%2,%3};"               \
        : "+f"(d[0]), "+f"(d[1]), "+f"(d[2]), "+f"(d[3])                      \
        : "r"(a0), "r"(a1), "r"(a2), "r"(a3), "r"(b0), "r"(b1))

__device__ __forceinline__ uint32_t split_pack2(float v0, float v1, int limb, float scale) {
    float s0 = v0 * scale, s1 = v1 * scale;
    __half h0 = __float2half_rn(s0), h1 = __float2half_rn(s1);
    __half r0, r1;
    if (limb == 0) { r0 = h0; r1 = h1; }
    else {
        r0 = __float2half_rn(s0 - __half2float(h0));
        r1 = __float2half_rn(s1 - __half2float(h1));
    }
    __half2 p = __halves2half2(r0, r1);
    return *(uint32_t*)&p;
}

// ---------------- kernel A: codewords + half squared norms ----------------
__global__ void compute_codewords(const float* __restrict__ dict,
                                  const float* __restrict__ counts) {
    int k = blockIdx.x;
    int t = threadIdx.x;
    float inv = 1.0f / counts[k];
    const float4* src = (const float4*)(dict + (size_t)k * DIM);
    float4*       dst = (float4*)(g_e + (size_t)k * DIM);
    float4 v = src[t];
    v.x *= inv; v.y *= inv; v.z *= inv; v.w *= inv;
    dst[t] = v;
    float s = v.x * v.x + v.y * v.y + v.z * v.z + v.w * v.w;
    #pragma unroll
    for (int o = 16; o; o >>= 1) s += __shfl_xor_sync(0xffffffffu, s, o);
    __shared__ float ws[4];
    if ((t & 31) == 0) ws[t >> 5] = s;
    __syncthreads();
    if (t == 0) g_h[k] = 0.5f * (ws[0] + ws[1] + ws[2] + ws[3]);
}

// ---------------- pack X into fragment-ordered fp16 limbs ----------------
// A uint32 index o: [mt(256)][c(32)][msub(8)][limb(2)][lane(32)][reg(4)]
// reg: 0=(r,kc) 1=(r+8,kc) 2=(r,kc+8) 3=(r+8,kc+8); r=lane/4, kc=(lane%4)*2
__global__ void split_x(const float* __restrict__ X) {
    int o = blockIdx.x * 256 + threadIdx.x;       // 16777216 total
    int reg  =  o        & 3;
    int lane = (o >> 2)  & 31;
    int limb = (o >> 7)  & 1;
    int msub = (o >> 8)  & 7;
    int c    = (o >> 11) & 31;
    int mt   =  o >> 16;
    int m = mt * 128 + msub * 16 + (lane >> 2) + (reg & 1) * 8;
    int k = c * 16 + (lane & 3) * 2 + (reg >> 1) * 8;
    const float* xp = X + (size_t)m * DIM + k;
    g_xp[o] = split_pack2(xp[0], xp[1], limb, XSCALE);
}

// B uint32 index o: [nt(32)][c(32)][nsub(32)][limb(2)][lane(32)][reg(2)]
// reg: 0=(kc..kc+1, n) 1=(kc+8..kc+9, n); n=lane/4, kc=(lane%4)*2
__global__ void split_e() {
    int o = blockIdx.x * 256 + threadIdx.x;       // 4194304 total
    int reg  =  o        & 1;
    int lane = (o >> 1)  & 31;
    int limb = (o >> 6)  & 1;
    int nsub = (o >> 7)  & 31;
    int c    = (o >> 12) & 31;
    int nt   =  o >> 17;
    int n = nt * 256 + nsub * 8 + (lane >> 2);
    int k = c * 16 + (lane & 3) * 2 + reg * 8;
    const float* ep = g_e + (size_t)n * DIM + k;
    g_ep[o] = split_pack2(ep[0], ep[1], limb, ESCALE);
}

// ---------------- kernel B: init scratch + new_dict = 0.995*dict ----------------
__global__ void init_kernel(const float* __restrict__ dict, float* __restrict__ out) {
    size_t i = (size_t)blockIdx.x * blockDim.x + threadIdx.x;
    size_t stride = (size_t)gridDim.x * blockDim.x;
    const size_t nd2 = (size_t)VOCAB * DIM / 2;
    float2* od = (float2*)(out + OFF_DICT);
    const float2* dd = (const float2*)dict;
    for (size_t j = i; j < nd2; j += stride) {
        float2 d = dd[j];
        d.x *= MOM; d.y *= MOM;
        od[j] = d;
    }
    for (size_t j = i; j < M_ROWS; j += stride) g_best[j] = 0ull;
    for (size_t j = i; j < VOCAB;  j += stride) g_cnt[j] = 0.0f;
    if (i == 0) g_loss = 0.0;
}

// ---------------- kernel C: 3-product fp16-limb mma GEMM + fused argmax ----------------
__global__ void __launch_bounds__(256, 1)
gemm_argmax_mma() {
    extern __shared__ char sm[];
    uint32_t smb = smem_u32(sm);
    float* h_s = (float*)(sm + SM_H);
    unsigned long long* sbest = (unsigned long long*)(sm + SM_BEST);
    const int tid = threadIdx.x, lane = tid & 31, w = tid >> 5;
    const int wm = w >> 2, wn = w & 3;           // 2 x 4 warps, warp tile 64x64
    const int nt = blockIdx.x, mt = blockIdx.y;

    for (int i = tid; i < TN; i += 256) h_s[i] = HSCALE * g_h[nt * TN + i];
    if (tid < TM) sbest[tid] = 0ull;

    const uint32_t* gA = g_xp + (size_t)(mt * NCHUNK) * 2048;
    const uint32_t* gB = g_ep + (size_t)(nt * NCHUNK) * 4096;

    float acc[4][8][4];
    #pragma unroll
    for (int i = 0; i < 4; i++)
        #pragma unroll
        for (int j = 0; j < 8; j++)
            #pragma unroll
            for (int r = 0; r < 4; r++) acc[i][j][r] = 0.0f;

    auto issue = [&](int c) {
        uint32_t sb = smb + (uint32_t)(c & 3) * STAGE_BYTES;
        const uint32_t* a = gA + c * 2048;
        const uint32_t* b = gB + c * 4096;
        cp16(sb +         tid * 16, a + tid * 4);
        cp16(sb +  4096 + tid * 16, a + 1024 + tid * 4);
        cp16(sb +  8192 + tid * 16, b + tid * 4);
        cp16(sb + 12288 + tid * 16, b + 1024 + tid * 4);
        cp16(sb + 16384 + tid * 16, b + 2048 + tid * 4);
        cp16(sb + 20480 + tid * 16, b + 3072 + tid * 4);
        CP_COMMIT();
    };

    issue(0); issue(1); issue(2);

    for (int c = 0; c < NCHUNK; c++) {
        if (c + 3 < NCHUNK) issue(c + 3);
        int rem = NCHUNK - 1 - c;
        if      (rem >= 3) CP_WAIT(3);
        else if (rem == 2) CP_WAIT(2);
        else if (rem == 1) CP_WAIT(1);
        else               CP_WAIT(0);
        __syncthreads();

        int sbase = (c & 3) * STAGE_BYTES;
        // B fragments for this warp's 8 n-subtiles (hi + lo)
        uint32_t bh[8][2], bl[8][2];
        #pragma unroll
        for (int j = 0; j < 8; j++) {
            int bo = sbase + 8192 + (wn * 8 + j) * 512 + lane * 8;
            uint2 vh = *(const uint2*)(sm + bo);
            uint2 vl = *(const uint2*)(sm + bo + 256);
            bh[j][0] = vh.x; bh[j][1] = vh.y;
            bl[j][0] = vl.x; bl[j][1] = vl.y;
        }
        #pragma unroll
        for (int i = 0; i < 4; i++) {
            int ao = sbase + (wm * 4 + i) * 1024 + lane * 16;
            uint4 ah = *(const uint4*)(sm + ao);
            uint4 al = *(const uint4*)(sm + ao + 512);
            #pragma unroll
            for (int j = 0; j < 8; j++) {
                MMA16(acc[i][j], ah.x, ah.y, ah.z, ah.w, bh[j][0], bh[j][1]);
                MMA16(acc[i][j], ah.x, ah.y, ah.z, ah.w, bl[j][0], bl[j][1]);
                MMA16(acc[i][j], al.x, al.y, al.z, al.w, bh[j][0], bh[j][1]);
            }
        }
        __syncthreads();
    }

    // ---- epilogue: streaming argmax over this 128x256 tile ----
    #pragma unroll
    for (int i = 0; i < 4; i++) {
        #pragma unroll
        for (int half = 0; half < 2; half++) {
            int row = wm * 64 + i * 16 + (lane >> 2) + half * 8;
            float bs = -1e30f;
            int   bc = 0;
            #pragma unroll
            for (int j = 0; j < 8; j++) {
                #pragma unroll
                for (int p = 0; p < 2; p++) {
                    int coll = wn * 64 + j * 8 + (lane & 3) * 2 + p;
                    float s = acc[i][j][half * 2 + p] - h_s[coll];
                    int col = nt * TN + coll;
                    if (s > bs || (s == bs && col < bc)) { bs = s; bc = col; }
                }
            }
            unsigned int ub = __float_as_uint(bs);
            ub = (ub & 0x80000000u) ? ~ub : (ub | 0x80000000u);
            unsigned long long key =
                ((unsigned long long)ub << 32) | (unsigned int)(VOCAB - 1 - bc);
            #pragma unroll
            for (int off = 1; off < 4; off <<= 1) {
                unsigned long long other = __shfl_xor_sync(0xffffffffu, key, off);
                if (other > key) key = other;
            }
            if ((lane & 3) == 0) atomicMax(&sbest[row], key);
        }
    }
    __syncthreads();
    if (tid < TM) atomicMax(&g_best[(size_t)mt * TM + tid], sbest[tid]);
}

// ---------------- kernel D: gather x_q, loss, histogram, scatter x_sum ----------------
__global__ void scatter_kernel(const float* __restrict__ X, float* __restrict__ out) {
    int gw   = ((int)blockIdx.x * blockDim.x + threadIdx.x) >> 5;  // row
    int lane = threadIdx.x & 31;
    __shared__ double lred[8];
    double lsum = 0.0;
    if (gw < M_ROWS) {
        unsigned long long key = g_best[gw];
        int k = VOCAB - 1 - (int)(key & 0xffffffffu);
        const float4* e4 = (const float4*)(g_e + (size_t)k * DIM);
        const float4* x4 = (const float4*)(X + (size_t)gw * DIM);
        float4*       q4 = (float4*)(out + (size_t)gw * DIM);
        float* nd = out + OFF_DICT + (size_t)k * DIM;
        float fs = 0.0f;
        #pragma unroll
        for (int c = lane; c < DIM / 4; c += 32) {
            float4 e = e4[c], x = x4[c];
            q4[c] = e;
            float dx = e.x - x.x, dy = e.y - x.y, dz = e.z - x.z, dw = e.w - x.w;
            fs += dx * dx + dy * dy + dz * dz + dw * dw;
            atomicAdd(nd + c * 4 + 0, x.x);
            atomicAdd(nd + c * 4 + 1, x.y);
            atomicAdd(nd + c * 4 + 2, x.z);
            atomicAdd(nd + c * 4 + 3, x.w);
        }
        #pragma unroll
        for (int o = 16; o; o >>= 1) fs += __shfl_xor_sync(0xffffffffu, fs, o);
        if (lane == 0) {
            atomicAdd(&g_cnt[k], 1.0f);
            lsum = (double)fs;
        }
    }
    int wid = threadIdx.x >> 5;
    if (lane == 0) lred[wid] = lsum;
    __syncthreads();
    if (threadIdx.x == 0) {
        double t = 0.0;
        for (int i = 0; i < 8; i++) t += lred[i];
        atomicAdd(&g_loss, t);
    }
}

// ---------------- kernel E: new_counts, loss, perplexity ----------------
__global__ void finalize_kernel(const float* __restrict__ counts, float* __restrict__ out) {
    __shared__ double red[32];
    __shared__ double s_total;
    int tid = threadIdx.x;
    double s = 0.0;
    for (int k = tid; k < VOCAB; k += 1024) {
        float nc = counts[k] * MOM + g_cnt[k];
        out[OFF_CNT + k] = nc;
        s += (double)nc;
    }
    #pragma unroll
    for (int o = 16; o; o >>= 1) s += __shfl_xor_sync(0xffffffffu, s, o);
    if ((tid & 31) == 0) red[tid >> 5] = s;
    __syncthreads();
    if (tid < 32) {
        double t = red[tid];
        #pragma unroll
        for (int o = 16; o; o >>= 1) t += __shfl_xor_sync(0xffffffffu, t, o);
        if (tid == 0) s_total = t;
    }
    __syncthreads();
    double total = s_total;
    double h = 0.0;
    for (int k = tid; k < VOCAB; k += 1024) {
        double p = (double)out[OFF_CNT + k] / total;
        h += p * log(p + 1e-10);
    }
    #pragma unroll
    for (int o = 16; o; o >>= 1) h += __shfl_xor_sync(0xffffffffu, h, o);
    if ((tid & 31) == 0) red[tid >> 5] = h;
    __syncthreads();
    if (tid == 0) {
        double t = 0.0;
        for (int i = 0; i < 32; i++) t += red[i];
        out[OFF_PERP] = (float)exp(-t);
        out[OFF_LOSS] = (float)(0.25 * g_loss / 16777216.0);
    }
}

// ---------------- launch ----------------
extern "C" void kernel_launch(void* const* d_in, const int* in_sizes, int n_in,
                              void* d_out, int out_size) {
    (void)in_sizes; (void)n_in; (void)out_size;
    const float* X      = (const float*)d_in[0];
    const float* dict   = (const float*)d_in[1];
    const float* counts = (const float*)d_in[2];
    float* out = (float*)d_out;

    cudaFuncSetAttribute(gemm_argmax_mma,
                         cudaFuncAttributeMaxDynamicSharedMemorySize, SM_TOTAL);

    compute_codewords<<<VOCAB, 128>>>(dict, counts);
    split_e<<<16384, 256>>>();
    split_x<<<65536, 256>>>(X);
    init_kernel<<<2048, 256>>>(dict, out);
    dim3 grid(VOCAB / TN, M_ROWS / TM);   // (32, 256)
    gemm_argmax_mma<<<grid, 256, SM_TOTAL>>>();
    scatter_kernel<<<M_ROWS * 32 / 256, 256>>>(X, out);
    finalize_kernel<<<1, 1024>>>(counts, out);
}

// round 7
// speedup vs baseline: 3.3197x; 1.5323x over previous
#include <cuda_runtime.h>
#include <cuda_fp16.h>
#include <math.h>
#include <stdint.h>

// ---------------- problem constants ----------------
#define VOCAB   8192
#define DIM     512
#define M_ROWS  32768          // 8*4096
#define MOM     0.995f
// output packing (flat f32, tuple order): x_q | loss | perplexity | new_dict | new_counts
#define OFF_LOSS 16777216ull
#define OFF_PERP 16777217ull
#define OFF_DICT 16777218ull
#define OFF_CNT  20971522ull   // OFF_DICT + VOCAB*DIM

// ---------------- GEMM tiling (pass 1, fp16-hi approx) ----------------
#define TM      128
#define TN      256
#define KC      16
#define NCHUNK  (DIM / KC)     // 32
#define MARGIN  0.02f          // >= 3x fully-aligned worst-case fp16 rounding error
#define CAP     16777216       // candidate capacity
// stage: A 4KB + B 8KB
#define STAGE_BYTES 12288
#define SM_H     49152
#define SM_BEST  50176
#define SM_TOTAL 51200

// ---------------- device scratch (static; no allocations) ----------------
__device__ float               g_e[VOCAB * DIM];
__device__ float               g_h[VOCAB];          // 0.5*||e||^2
__device__ unsigned long long  g_best[M_ROWS];      // approx (pass-1) packed keys
__device__ unsigned long long  g_best2[M_ROWS];     // exact (pass-2) packed keys
__device__ float               g_cnt[VOCAB];
__device__ double              g_loss;
__device__ unsigned int        g_ncand;
__device__ uint32_t            g_cand[CAP];         // row*8192+col
// fragment-packed fp16 hi-limb operands
__device__ uint32_t            g_xh[M_ROWS * DIM / 2];   // 32MB
__device__ uint32_t            g_eh[VOCAB  * DIM / 2];   // 8MB

// ---------------- helpers ----------------
__device__ __forceinline__ uint32_t smem_u32(const void* p) {
    uint32_t a;
    asm("{ .reg .u64 t; cvta.to.shared.u64 t, %1; cvt.u32.u64 %0, t; }" : "=r"(a) : "l"(p));
    return a;
}
__device__ __forceinline__ void cp16(uint32_t dst, const void* src) {
    asm volatile("cp.async.ca.shared.global [%0], [%1], 16;" :: "r"(dst), "l"(src));
}
#define CP_COMMIT() asm volatile("cp.async.commit_group;")
#define CP_WAIT(n)  asm volatile("cp.async.wait_group %0;" :: "n"(n))

#define MMA16(d, a0, a1, a2, a3, b0, b1)                                      \
    asm volatile(                                                             \
        "mma.sync.aligned.m16n8k16.row.col.f32.f16.f16.f32 "                  \
        "{%0,%1,%2,%3}, {%4,%5,%6,%7}, {%8,%9}, {%0,%1,%2,%3};"               \
        : "+f"(d[0]), "+f"(d[1]), "+f"(d[2]), "+f"(d[3])                      \
        : "r"(a0), "r"(a1), "r"(a2), "r"(a3), "r"(b0), "r"(b1))

__device__ __forceinline__ unsigned int fkey(float s) {
    unsigned int ub = __float_as_uint(s);
    return (ub & 0x80000000u) ? ~ub : (ub | 0x80000000u);
}
__device__ __forceinline__ float keyscore(unsigned long long k) {
    unsigned int ub = (unsigned int)(k >> 32);
    unsigned int orig = (ub & 0x80000000u) ? (ub & 0x7fffffffu) : ~ub;
    return __uint_as_float(orig);   // k==0 -> -NaN; callers use fmaxf
}
__device__ __forceinline__ uint32_t pack_h2(float v0, float v1) {
    __half2 p = __halves2half2(__float2half_rn(v0), __float2half_rn(v1));
    return *(uint32_t*)&p;
}

// ---------------- kernel A: codewords + half squared norms ----------------
__global__ void compute_codewords(const float* __restrict__ dict,
                                  const float* __restrict__ counts) {
    int k = blockIdx.x;
    int t = threadIdx.x;
    float inv = 1.0f / counts[k];
    const float4* src = (const float4*)(dict + (size_t)k * DIM);
    float4*       dst = (float4*)(g_e + (size_t)k * DIM);
    float4 v = src[t];
    v.x *= inv; v.y *= inv; v.z *= inv; v.w *= inv;
    dst[t] = v;
    float s = v.x * v.x + v.y * v.y + v.z * v.z + v.w * v.w;
    #pragma unroll
    for (int o = 16; o; o >>= 1) s += __shfl_xor_sync(0xffffffffu, s, o);
    __shared__ float ws[4];
    if ((t & 31) == 0) ws[t >> 5] = s;
    __syncthreads();
    if (t == 0) g_h[k] = 0.5f * (ws[0] + ws[1] + ws[2] + ws[3]);
}

// ---------------- pack X / E into fragment-ordered fp16 hi limbs ----------------
// A u32 index: [mt(256)][c(32)][msub(8)][lane(32)][reg(4)]
__global__ void split_x(const float* __restrict__ X) {
    int o = blockIdx.x * 256 + threadIdx.x;       // 8388608 total
    int reg  =  o        & 3;
    int lane = (o >> 2)  & 31;
    int msub = (o >> 7)  & 7;
    int c    = (o >> 10) & 31;
    int mt   =  o >> 15;
    int m = mt * 128 + msub * 16 + (lane >> 2) + (reg & 1) * 8;
    int k = c * 16 + (lane & 3) * 2 + (reg >> 1) * 8;
    const float* xp = X + (size_t)m * DIM + k;
    g_xh[o] = pack_h2(xp[0], xp[1]);
}

// B u32 index: [nt(32)][c(32)][nsub(32)][lane(32)][reg(2)]
__global__ void split_e() {
    int o = blockIdx.x * 256 + threadIdx.x;       // 2097152 total
    int reg  =  o        & 1;
    int lane = (o >> 1)  & 31;
    int nsub = (o >> 6)  & 31;
    int c    = (o >> 11) & 31;
    int nt   =  o >> 16;
    int n = nt * 256 + nsub * 8 + (lane >> 2);
    int k = c * 16 + (lane & 3) * 2 + reg * 8;
    const float* ep = g_e + (size_t)n * DIM + k;
    g_eh[o] = pack_h2(ep[0], ep[1]);
}

// ---------------- kernel B: init scratch + new_dict = 0.995*dict ----------------
__global__ void init_kernel(const float* __restrict__ dict, float* __restrict__ out) {
    size_t i = (size_t)blockIdx.x * blockDim.x + threadIdx.x;
    size_t stride = (size_t)gridDim.x * blockDim.x;
    const size_t nd2 = (size_t)VOCAB * DIM / 2;
    float2* od = (float2*)(out + OFF_DICT);
    const float2* dd = (const float2*)dict;
    for (size_t j = i; j < nd2; j += stride) {
        float2 d = dd[j];
        d.x *= MOM; d.y *= MOM;
        od[j] = d;
    }
    for (size_t j = i; j < M_ROWS; j += stride) { g_best[j] = 0ull; g_best2[j] = 0ull; }
    for (size_t j = i; j < VOCAB;  j += stride) g_cnt[j] = 0.0f;
    if (i == 0) { g_loss = 0.0; g_ncand = 0u; }
}

// ---------------- kernel C: pass-1 fp16-hi approx GEMM + candidate harvest ----------------
__global__ void __launch_bounds__(512, 1)
gemm_approx() {
    extern __shared__ char sm[];
    uint32_t smb = smem_u32(sm);
    float* h_s = (float*)(sm + SM_H);
    unsigned long long* sbest = (unsigned long long*)(sm + SM_BEST);
    const int tid = threadIdx.x, lane = tid & 31, w = tid >> 5;
    const int wm = w >> 3, wn = w & 7;           // 2 x 8 warps, warp tile 64x32
    const int mt = blockIdx.x, nt = blockIdx.y;  // mt-major: nt tiles of a row spread over waves

    for (int i = tid; i < TN; i += 512) h_s[i] = g_h[nt * TN + i];
    if (tid < TM) sbest[tid] = 0ull;

    const uint32_t* gA = g_xh + (size_t)(mt * NCHUNK) * 1024;
    const uint32_t* gB = g_eh + (size_t)(nt * NCHUNK) * 2048;

    float acc[4][4][4];
    #pragma unroll
    for (int i = 0; i < 4; i++)
        #pragma unroll
        for (int j = 0; j < 4; j++)
            #pragma unroll
            for (int r = 0; r < 4; r++) acc[i][j][r] = 0.0f;

    auto issue = [&](int c) {
        uint32_t sb = smb + (uint32_t)(c & 3) * STAGE_BYTES;
        const uint32_t* a = gA + c * 1024;
        const uint32_t* b = gB + c * 2048;
        if (tid < 256) cp16(sb + tid * 16, a + tid * 4);
        cp16(sb + 4096 + tid * 16, b + tid * 4);
        CP_COMMIT();
    };

    issue(0); issue(1); issue(2);

    for (int c = 0; c < NCHUNK; c++) {
        if (c + 3 < NCHUNK) issue(c + 3);
        int rem = NCHUNK - 1 - c;
        if      (rem >= 3) CP_WAIT(3);
        else if (rem == 2) CP_WAIT(2);
        else if (rem == 1) CP_WAIT(1);
        else               CP_WAIT(0);
        __syncthreads();

        int sbase = (c & 3) * STAGE_BYTES;
        uint2 bf[4];
        #pragma unroll
        for (int j = 0; j < 4; j++)
            bf[j] = *(const uint2*)(sm + sbase + 4096 + (wn * 4 + j) * 256 + lane * 8);
        uint4 af[4];
        #pragma unroll
        for (int i = 0; i < 4; i++)
            af[i] = *(const uint4*)(sm + sbase + (wm * 4 + i) * 512 + lane * 16);
        #pragma unroll
        for (int i = 0; i < 4; i++)
            #pragma unroll
            for (int j = 0; j < 4; j++)
                MMA16(acc[i][j], af[i].x, af[i].y, af[i].z, af[i].w, bf[j].x, bf[j].y);
        __syncthreads();
    }

    // ---- epilogue 1: tile-local per-row best ----
    #pragma unroll
    for (int i = 0; i < 4; i++) {
        #pragma unroll
        for (int half = 0; half < 2; half++) {
            int rowl = wm * 64 + i * 16 + (lane >> 2) + half * 8;
            float bs = -1e30f; int bc = 0;
            #pragma unroll
            for (int j = 0; j < 4; j++)
                #pragma unroll
                for (int p = 0; p < 2; p++) {
                    int coll = wn * 32 + j * 8 + (lane & 3) * 2 + p;
                    float s = acc[i][j][half * 2 + p] - h_s[coll];
                    int col = nt * TN + coll;
                    if (s > bs || (s == bs && col < bc)) { bs = s; bc = col; }
                }
            unsigned long long key =
                ((unsigned long long)fkey(bs) << 32) | (unsigned int)(VOCAB - 1 - bc);
            #pragma unroll
            for (int off = 1; off < 4; off <<= 1) {
                unsigned long long other = __shfl_xor_sync(0xffffffffu, key, off);
                if (other > key) key = other;
            }
            if ((lane & 3) == 0) atomicMax(&sbest[rowl], key);
        }
    }
    __syncthreads();

    // ---- epilogue 2: candidate harvest (margin below max(tile best, global approx)) ----
    #pragma unroll
    for (int i = 0; i < 4; i++) {
        #pragma unroll
        for (int half = 0; half < 2; half++) {
            int rowl = wm * 64 + i * 16 + (lane >> 2) + half * 8;
            int rowg = mt * TM + rowl;
            float tb = keyscore(sbest[rowl]);
            float gb = keyscore(g_best[rowg]);          // racy lower bound: safe
            float thr = fmaxf(tb, gb) - MARGIN;
            #pragma unroll
            for (int j = 0; j < 4; j++)
                #pragma unroll
                for (int p = 0; p < 2; p++) {
                    int coll = wn * 32 + j * 8 + (lane & 3) * 2 + p;
                    float s = acc[i][j][half * 2 + p] - h_s[coll];
                    bool pred = (s >= thr);
                    unsigned int m = __ballot_sync(0xffffffffu, pred);
                    if (m) {
                        int leader = __ffs(m) - 1;
                        unsigned int base = 0;
                        if (lane == leader) base = atomicAdd(&g_ncand, (unsigned)__popc(m));
                        base = __shfl_sync(0xffffffffu, base, leader);
                        if (pred) {
                            unsigned int idx = base + __popc(m & ((1u << lane) - 1));
                            if (idx < CAP)
                                g_cand[idx] = (unsigned)rowg * 8192u + (unsigned)(nt * TN + coll);
                        }
                    }
                }
        }
    }
    __syncthreads();
    if (tid < TM) atomicMax(&g_best[(size_t)mt * TM + tid], sbest[tid]);
}

// ---------------- kernel C2: exact fp32 rescore of candidates ----------------
__global__ void rescore(const float* __restrict__ X) {
    int gw   = ((int)blockIdx.x * blockDim.x + threadIdx.x) >> 5;
    int nw   = (gridDim.x * blockDim.x) >> 5;
    int lane = threadIdx.x & 31;
    unsigned int n = g_ncand;
    if (n > CAP) n = CAP;
    for (unsigned int c = gw; c < n; c += nw) {
        uint32_t rc = g_cand[c];
        int row = rc >> 13, col = rc & 8191;
        const float4* xr = (const float4*)(X + (size_t)row * DIM);
        const float4* er = (const float4*)(g_e + (size_t)col * DIM);
        float s = 0.0f;
        #pragma unroll
        for (int t = lane; t < DIM / 4; t += 32) {
            float4 x = xr[t], e = er[t];
            s += x.x * e.x + x.y * e.y + x.z * e.z + x.w * e.w;
        }
        #pragma unroll
        for (int o = 16; o; o >>= 1) s += __shfl_xor_sync(0xffffffffu, s, o);
        if (lane == 0) {
            float sc = s - g_h[col];
            unsigned long long key =
                ((unsigned long long)fkey(sc) << 32) | (unsigned int)(VOCAB - 1 - col);
            atomicMax(&g_best2[row], key);
        }
    }
}

// ---------------- kernel D: gather x_q, loss, histogram, scatter x_sum ----------------
__global__ void scatter_kernel(const float* __restrict__ X, float* __restrict__ out) {
    int gw   = ((int)blockIdx.x * blockDim.x + threadIdx.x) >> 5;  // row
    int lane = threadIdx.x & 31;
    __shared__ double lred[8];
    double lsum = 0.0;
    if (gw < M_ROWS) {
        unsigned long long key = g_best2[gw];
        int k = VOCAB - 1 - (int)(key & 0xffffffffu);
        const float4* e4 = (const float4*)(g_e + (size_t)k * DIM);
        const float4* x4 = (const float4*)(X + (size_t)gw * DIM);
        float4*       q4 = (float4*)(out + (size_t)gw * DIM);
        float* nd = out + OFF_DICT + (size_t)k * DIM;
        float fs = 0.0f;
        #pragma unroll
        for (int c = lane; c < DIM / 4; c += 32) {
            float4 e = e4[c], x = x4[c];
            q4[c] = e;
            float dx = e.x - x.x, dy = e.y - x.y, dz = e.z - x.z, dw = e.w - x.w;
            fs += dx * dx + dy * dy + dz * dz + dw * dw;
            atomicAdd(nd + c * 4 + 0, x.x);
            atomicAdd(nd + c * 4 + 1, x.y);
            atomicAdd(nd + c * 4 + 2, x.z);
            atomicAdd(nd + c * 4 + 3, x.w);
        }
        #pragma unroll
        for (int o = 16; o; o >>= 1) fs += __shfl_xor_sync(0xffffffffu, fs, o);
        if (lane == 0) {
            atomicAdd(&g_cnt[k], 1.0f);
            lsum = (double)fs;
        }
    }
    int wid = threadIdx.x >> 5;
    if (lane == 0) lred[wid] = lsum;
    __syncthreads();
    if (threadIdx.x == 0) {
        double t = 0.0;
        for (int i = 0; i < 8; i++) t += lred[i];
        atomicAdd(&g_loss, t);
    }
}

// ---------------- kernel E: new_counts, loss, perplexity ----------------
__global__ void finalize_kernel(const float* __restrict__ counts, float* __restrict__ out) {
    __shared__ double red[32];
    __shared__ double s_total;
    int tid = threadIdx.x;
    double s = 0.0;
    for (int k = tid; k < VOCAB; k += 1024) {
        float nc = counts[k] * MOM + g_cnt[k];
        out[OFF_CNT + k] = nc;
        s += (double)nc;
    }
    #pragma unroll
    for (int o = 16; o; o >>= 1) s += __shfl_xor_sync(0xffffffffu, s, o);
    if ((tid & 31) == 0) red[tid >> 5] = s;
    __syncthreads();
    if (tid < 32) {
        double t = red[tid];
        #pragma unroll
        for (int o = 16; o; o >>= 1) t += __shfl_xor_sync(0xffffffffu, t, o);
        if (tid == 0) s_total = t;
    }
    __syncthreads();
    double total = s_total;
    double h = 0.0;
    for (int k = tid; k < VOCAB; k += 1024) {
        double p = (double)out[OFF_CNT + k] / total;
        h += p * log(p + 1e-10);
    }
    #pragma unroll
    for (int o = 16; o; o >>= 1) h += __shfl_xor_sync(0xffffffffu, h, o);
    if ((tid & 31) == 0) red[tid >> 5] = h;
    __syncthreads();
    if (tid == 0) {
        double t = 0.0;
        for (int i = 0; i < 32; i++) t += red[i];
        out[OFF_PERP] = (float)exp(-t);
        out[OFF_LOSS] = (float)(0.25 * g_loss / 16777216.0);
    }
}

// ---------------- launch ----------------
extern "C" void kernel_launch(void* const* d_in, const int* in_sizes, int n_in,
                              void* d_out, int out_size) {
    (void)in_sizes; (void)n_in; (void)out_size;
    const float* X      = (const float*)d_in[0];
    const float* dict   = (const float*)d_in[1];
    const float* counts = (const float*)d_in[2];
    float* out = (float*)d_out;

    cudaFuncSetAttribute(gemm_approx,
                         cudaFuncAttributeMaxDynamicSharedMemorySize, SM_TOTAL);

    compute_codewords<<<VOCAB, 128>>>(dict, counts);
    split_e<<<8192, 256>>>();
    split_x<<<32768, 256>>>(X);
    init_kernel<<<2048, 256>>>(dict, out);
    dim3 grid(M_ROWS / TM, VOCAB / TN);   // (256, 32), mt-major
    gemm_approx<<<grid, 512, SM_TOTAL>>>();
    rescore<<<2048, 256>>>(X);
    scatter_kernel<<<M_ROWS * 32 / 256, 256>>>(X, out);
    finalize_kernel<<<1, 1024>>>(counts, out);
}

// round 8
// speedup vs baseline: 4.0102x; 1.2080x over previous
#include <cuda_runtime.h>
#include <cuda_fp16.h>
#include <math.h>
#include <stdint.h>

// ---------------- problem constants ----------------
#define VOCAB   8192
#define DIM     512
#define M_ROWS  32768          // 8*4096
#define MOM     0.995f
// output packing (flat f32, tuple order): x_q | loss | perplexity | new_dict | new_counts
#define OFF_LOSS 16777216ull
#define OFF_PERP 16777217ull
#define OFF_DICT 16777218ull
#define OFF_CNT  20971522ull   // OFF_DICT + VOCAB*DIM

// ---------------- GEMM tiling (pass 1, fp16-hi approx) ----------------
#define TM      128
#define TN      256
#define KC      32             // floats per K chunk
#define NCHUNK  (DIM / KC)     // 16
#define MARGIN  0.02f          // >= 3x fully-aligned worst-case fp16 rounding error
#define CAP     16777216       // candidate capacity
// stage: A 8KB + B 16KB ; 3 stages
#define STAGE_BYTES 24576
#define SM_H     73728         // 3*24576
#define SM_BEST  74752
#define SM_TOTAL 75776

// ---------------- device scratch (static; no allocations) ----------------
__device__ float               g_e[VOCAB * DIM];
__device__ float               g_h[VOCAB];          // 0.5*||e||^2
__device__ unsigned long long  g_best[M_ROWS];      // approx (pass-1) packed keys
__device__ unsigned long long  g_best2[M_ROWS];     // exact (pass-2) packed keys
__device__ float               g_cnt[VOCAB];
__device__ double              g_loss;
__device__ unsigned int        g_ncand;
__device__ uint32_t            g_cand[CAP];         // row*8192+col
// fragment-packed fp16 hi-limb operands
__device__ uint32_t            g_xh[M_ROWS * DIM / 2];   // 32MB
__device__ uint32_t            g_eh[VOCAB  * DIM / 2];   // 8MB

// ---------------- helpers ----------------
__device__ __forceinline__ uint32_t smem_u32(const void* p) {
    uint32_t a;
    asm("{ .reg .u64 t; cvta.to.shared.u64 t, %1; cvt.u32.u64 %0, t; }" : "=r"(a) : "l"(p));
    return a;
}
__device__ __forceinline__ void cp16(uint32_t dst, const void* src) {
    asm volatile("cp.async.ca.shared.global [%0], [%1], 16;" :: "r"(dst), "l"(src));
}
#define CP_COMMIT() asm volatile("cp.async.commit_group;")
#define CP_WAIT(n)  asm volatile("cp.async.wait_group %0;" :: "n"(n))

#define MMA16(d, a0, a1, a2, a3, b0, b1)                                      \
    asm volatile(                                                             \
        "mma.sync.aligned.m16n8k16.row.col.f32.f16.f16.f32 "                  \
        "{%0,%1,%2,%3}, {%4,%5,%6,%7}, {%8,%9}, {%0,%1,%2,%3};"               \
        : "+f"(d[0]), "+f"(d[1]), "+f"(d[2]), "+f"(d[3])                      \
        : "r"(a0), "r"(a1), "r"(a2), "r"(a3), "r"(b0), "r"(b1))

__device__ __forceinline__ unsigned int fkey(float s) {
    unsigned int ub = __float_as_uint(s);
    return (ub & 0x80000000u) ? ~ub : (ub | 0x80000000u);
}
__device__ __forceinline__ float keyscore(unsigned long long k) {
    unsigned int ub = (unsigned int)(k >> 32);
    unsigned int orig = (ub & 0x80000000u) ? (ub & 0x7fffffffu) : ~ub;
    return __uint_as_float(orig);   // k==0 -> -NaN; callers use fmaxf
}
__device__ __forceinline__ uint32_t pack_h2(float v0, float v1) {
    __half2 p = __halves2half2(__float2half_rn(v0), __float2half_rn(v1));
    return *(uint32_t*)&p;
}

// ---------------- kernel A: codewords + half squared norms ----------------
__global__ void compute_codewords(const float* __restrict__ dict,
                                  const float* __restrict__ counts) {
    int k = blockIdx.x;
    int t = threadIdx.x;
    float inv = 1.0f / counts[k];
    const float4* src = (const float4*)(dict + (size_t)k * DIM);
    float4*       dst = (float4*)(g_e + (size_t)k * DIM);
    float4 v = src[t];
    v.x *= inv; v.y *= inv; v.z *= inv; v.w *= inv;
    dst[t] = v;
    float s = v.x * v.x + v.y * v.y + v.z * v.z + v.w * v.w;
    #pragma unroll
    for (int o = 16; o; o >>= 1) s += __shfl_xor_sync(0xffffffffu, s, o);
    __shared__ float ws[4];
    if ((t & 31) == 0) ws[t >> 5] = s;
    __syncthreads();
    if (t == 0) g_h[k] = 0.5f * (ws[0] + ws[1] + ws[2] + ws[3]);
}

// ---------------- pack X / E into fragment-ordered fp16 hi limbs ----------------
// A u32 index: [mt(256)][c(16)][msub(8)][ks(2)][lane(32)][reg(4)]
__global__ void split_x(const float* __restrict__ X) {
    int o = blockIdx.x * 256 + threadIdx.x;       // 8388608 total
    int reg  =  o        & 3;
    int lane = (o >> 2)  & 31;
    int ks   = (o >> 7)  & 1;
    int msub = (o >> 8)  & 7;
    int c    = (o >> 11) & 15;
    int mt   =  o >> 15;
    int m = mt * 128 + msub * 16 + (lane >> 2) + (reg & 1) * 8;
    int k = c * 32 + ks * 16 + (lane & 3) * 2 + (reg >> 1) * 8;
    const float* xp = X + (size_t)m * DIM + k;
    g_xh[o] = pack_h2(xp[0], xp[1]);
}

// B u32 index: [nt(32)][c(16)][nsub(32)][ks(2)][lane(32)][reg(2)]
__global__ void split_e() {
    int o = blockIdx.x * 256 + threadIdx.x;       // 2097152 total
    int reg  =  o        & 1;
    int lane = (o >> 1)  & 31;
    int ks   = (o >> 6)  & 1;
    int nsub = (o >> 7)  & 31;
    int c    = (o >> 12) & 15;
    int nt   =  o >> 16;
    int n = nt * 256 + nsub * 8 + (lane >> 2);
    int k = c * 32 + ks * 16 + (lane & 3) * 2 + reg * 8;
    const float* ep = g_e + (size_t)n * DIM + k;
    g_eh[o] = pack_h2(ep[0], ep[1]);
}

// ---------------- kernel B: init scratch + new_dict = 0.995*dict ----------------
__global__ void init_kernel(const float* __restrict__ dict, float* __restrict__ out) {
    size_t i = (size_t)blockIdx.x * blockDim.x + threadIdx.x;
    size_t stride = (size_t)gridDim.x * blockDim.x;
    const size_t nd2 = (size_t)VOCAB * DIM / 2;
    float2* od = (float2*)(out + OFF_DICT);
    const float2* dd = (const float2*)dict;
    for (size_t j = i; j < nd2; j += stride) {
        float2 d = dd[j];
        d.x *= MOM; d.y *= MOM;
        od[j] = d;
    }
    for (size_t j = i; j < M_ROWS; j += stride) { g_best[j] = 0ull; g_best2[j] = 0ull; }
    for (size_t j = i; j < VOCAB;  j += stride) g_cnt[j] = 0.0f;
    if (i == 0) { g_loss = 0.0; g_ncand = 0u; }
}

// ---------------- kernel C: pass-1 fp16-hi approx GEMM + candidate harvest ----------------
__global__ void __launch_bounds__(512, 1)
gemm_approx() {
    extern __shared__ char sm[];
    uint32_t smb = smem_u32(sm);
    float* h_s = (float*)(sm + SM_H);
    unsigned long long* sbest = (unsigned long long*)(sm + SM_BEST);
    const int tid = threadIdx.x, lane = tid & 31, w = tid >> 5;
    const int wm = w >> 3, wn = w & 7;           // 2 x 8 warps, warp tile 64x32
    const int mt = blockIdx.x, nt = blockIdx.y;  // mt-major: nt tiles of a row spread over waves

    for (int i = tid; i < TN; i += 512) h_s[i] = g_h[nt * TN + i];
    if (tid < TM) sbest[tid] = 0ull;

    const uint32_t* gA = g_xh + (size_t)(mt * NCHUNK) * 2048;
    const uint32_t* gB = g_eh + (size_t)(nt * NCHUNK) * 4096;

    float acc[4][4][4];
    #pragma unroll
    for (int i = 0; i < 4; i++)
        #pragma unroll
        for (int j = 0; j < 4; j++)
            #pragma unroll
            for (int r = 0; r < 4; r++) acc[i][j][r] = 0.0f;

    auto issue = [&](int c) {
        uint32_t sb = smb + (uint32_t)(c % 3) * STAGE_BYTES;
        const uint32_t* a = gA + c * 2048;
        const uint32_t* b = gB + c * 4096;
        cp16(sb + tid * 16, a + tid * 4);                     // A: 8KB
        cp16(sb + 8192 + tid * 16, b + tid * 4);              // B: 16KB
        cp16(sb + 8192 + 8192 + tid * 16, b + 2048 + tid * 4);
        CP_COMMIT();
    };

    issue(0); issue(1);

    for (int c = 0; c < NCHUNK; c++) {
        // complete group c (leave at most the newest one pending)
        if (c == NCHUNK - 1) CP_WAIT(0);
        else                 CP_WAIT(1);
        __syncthreads();                 // all warps done reading chunk c-1
        if (c + 2 < NCHUNK) issue(c + 2);   // overwrites stage (c-1)%3: safe

        int sbase = (c % 3) * STAGE_BYTES;
        #pragma unroll
        for (int ks = 0; ks < 2; ks++) {
            uint2 bf[4];
            #pragma unroll
            for (int j = 0; j < 4; j++)
                bf[j] = *(const uint2*)(sm + sbase + 8192 +
                                        (wn * 4 + j) * 512 + ks * 256 + lane * 8);
            uint4 af[4];
            #pragma unroll
            for (int i = 0; i < 4; i++)
                af[i] = *(const uint4*)(sm + sbase +
                                        (wm * 4 + i) * 1024 + ks * 512 + lane * 16);
            #pragma unroll
            for (int i = 0; i < 4; i++)
                #pragma unroll
                for (int j = 0; j < 4; j++)
                    MMA16(acc[i][j], af[i].x, af[i].y, af[i].z, af[i].w, bf[j].x, bf[j].y);
        }
    }
    __syncthreads();

    // ---- epilogue 1: tile-local per-row best ----
    #pragma unroll
    for (int i = 0; i < 4; i++) {
        #pragma unroll
        for (int half = 0; half < 2; half++) {
            int rowl = wm * 64 + i * 16 + (lane >> 2) + half * 8;
            float bs = -1e30f; int bc = 0;
            #pragma unroll
            for (int j = 0; j < 4; j++)
                #pragma unroll
                for (int p = 0; p < 2; p++) {
                    int coll = wn * 32 + j * 8 + (lane & 3) * 2 + p;
                    float s = acc[i][j][half * 2 + p] - h_s[coll];
                    int col = nt * TN + coll;
                    if (s > bs || (s == bs && col < bc)) { bs = s; bc = col; }
                }
            unsigned long long key =
                ((unsigned long long)fkey(bs) << 32) | (unsigned int)(VOCAB - 1 - bc);
            #pragma unroll
            for (int off = 1; off < 4; off <<= 1) {
                unsigned long long other = __shfl_xor_sync(0xffffffffu, key, off);
                if (other > key) key = other;
            }
            if ((lane & 3) == 0) atomicMax(&sbest[rowl], key);
        }
    }
    __syncthreads();

    // ---- epilogue 2: candidate harvest (margin below max(tile best, global approx)) ----
    #pragma unroll
    for (int i = 0; i < 4; i++) {
        #pragma unroll
        for (int half = 0; half < 2; half++) {
            int rowl = wm * 64 + i * 16 + (lane >> 2) + half * 8;
            int rowg = mt * TM + rowl;
            float tb = keyscore(sbest[rowl]);
            float gb = keyscore(g_best[rowg]);          // racy lower bound: safe
            float thr = fmaxf(tb, gb) - MARGIN;
            #pragma unroll
            for (int j = 0; j < 4; j++)
                #pragma unroll
                for (int p = 0; p < 2; p++) {
                    int coll = wn * 32 + j * 8 + (lane & 3) * 2 + p;
                    float s = acc[i][j][half * 2 + p] - h_s[coll];
                    bool pred = (s >= thr);
                    unsigned int m = __ballot_sync(0xffffffffu, pred);
                    if (m) {
                        int leader = __ffs(m) - 1;
                        unsigned int base = 0;
                        if (lane == leader) base = atomicAdd(&g_ncand, (unsigned)__popc(m));
                        base = __shfl_sync(0xffffffffu, base, leader);
                        if (pred) {
                            unsigned int idx = base + __popc(m & ((1u << lane) - 1));
                            if (idx < CAP)
                                g_cand[idx] = (unsigned)rowg * 8192u + (unsigned)(nt * TN + coll);
                        }
                    }
                }
        }
    }
    __syncthreads();
    if (tid < TM) atomicMax(&g_best[(size_t)mt * TM + tid], sbest[tid]);
}

// ---------------- kernel C2: exact fp32 rescore of candidates ----------------
__global__ void rescore(const float* __restrict__ X) {
    int gw   = ((int)blockIdx.x * blockDim.x + threadIdx.x) >> 5;
    int nw   = (gridDim.x * blockDim.x) >> 5;
    int lane = threadIdx.x & 31;
    unsigned int n = g_ncand;
    if (n > CAP) n = CAP;
    for (unsigned int c = gw; c < n; c += nw) {
        uint32_t rc = g_cand[c];
        int row = rc >> 13, col = rc & 8191;
        const float4* xr = (const float4*)(X + (size_t)row * DIM);
        const float4* er = (const float4*)(g_e + (size_t)col * DIM);
        float s = 0.0f;
        #pragma unroll
        for (int t = lane; t < DIM / 4; t += 32) {
            float4 x = xr[t], e = er[t];
            s += x.x * e.x + x.y * e.y + x.z * e.z + x.w * e.w;
        }
        #pragma unroll
        for (int o = 16; o; o >>= 1) s += __shfl_xor_sync(0xffffffffu, s, o);
        if (lane == 0) {
            float sc = s - g_h[col];
            unsigned long long key =
                ((unsigned long long)fkey(sc) << 32) | (unsigned int)(VOCAB - 1 - col);
            atomicMax(&g_best2[row], key);
        }
    }
}

// ---------------- kernel D: gather x_q, loss, histogram, scatter x_sum ----------------
__global__ void scatter_kernel(const float* __restrict__ X, float* __restrict__ out) {
    int gw   = ((int)blockIdx.x * blockDim.x + threadIdx.x) >> 5;  // row
    int lane = threadIdx.x & 31;
    __shared__ double lred[8];
    double lsum = 0.0;
    if (gw < M_ROWS) {
        unsigned long long key = g_best2[gw];
        int k = VOCAB - 1 - (int)(key & 0xffffffffu);
        const float4* e4 = (const float4*)(g_e + (size_t)k * DIM);
        const float4* x4 = (const float4*)(X + (size_t)gw * DIM);
        float4*       q4 = (float4*)(out + (size_t)gw * DIM);
        float* nd = out + OFF_DICT + (size_t)k * DIM;
        float fs = 0.0f;
        #pragma unroll
        for (int c = lane; c < DIM / 4; c += 32) {
            float4 e = e4[c], x = x4[c];
            q4[c] = e;
            float dx = e.x - x.x, dy = e.y - x.y, dz = e.z - x.z, dw = e.w - x.w;
            fs += dx * dx + dy * dy + dz * dz + dw * dw;
            atomicAdd(nd + c * 4 + 0, x.x);
            atomicAdd(nd + c * 4 + 1, x.y);
            atomicAdd(nd + c * 4 + 2, x.z);
            atomicAdd(nd + c * 4 + 3, x.w);
        }
        #pragma unroll
        for (int o = 16; o; o >>= 1) fs += __shfl_xor_sync(0xffffffffu, fs, o);
        if (lane == 0) {
            atomicAdd(&g_cnt[k], 1.0f);
            lsum = (double)fs;
        }
    }
    int wid = threadIdx.x >> 5;
    if (lane == 0) lred[wid] = lsum;
    __syncthreads();
    if (threadIdx.x == 0) {
        double t = 0.0;
        for (int i = 0; i < 8; i++) t += lred[i];
        atomicAdd(&g_loss, t);
    }
}

// ---------------- kernel E: new_counts, loss, perplexity ----------------
__global__ void finalize_kernel(const float* __restrict__ counts, float* __restrict__ out) {
    __shared__ double red[32];
    __shared__ double s_total;
    int tid = threadIdx.x;
    double s = 0.0;
    for (int k = tid; k < VOCAB; k += 1024) {
        float nc = counts[k] * MOM + g_cnt[k];
        out[OFF_CNT + k] = nc;
        s += (double)nc;
    }
    #pragma unroll
    for (int o = 16; o; o >>= 1) s += __shfl_xor_sync(0xffffffffu, s, o);
    if ((tid & 31) == 0) red[tid >> 5] = s;
    __syncthreads();
    if (tid < 32) {
        double t = red[tid];
        #pragma unroll
        for (int o = 16; o; o >>= 1) t += __shfl_xor_sync(0xffffffffu, t, o);
        if (tid == 0) s_total = t;
    }
    __syncthreads();
    double total = s_total;
    double h = 0.0;
    for (int k = tid; k < VOCAB; k += 1024) {
        double p = (double)out[OFF_CNT + k] / total;
        h += p * log(p + 1e-10);
    }
    #pragma unroll
    for (int o = 16; o; o >>= 1) h += __shfl_xor_sync(0xffffffffu, h, o);
    if ((tid & 31) == 0) red[tid >> 5] = h;
    __syncthreads();
    if (tid == 0) {
        double t = 0.0;
        for (int i = 0; i < 32; i++) t += red[i];
        out[OFF_PERP] = (float)exp(-t);
        out[OFF_LOSS] = (float)(0.25 * g_loss / 16777216.0);
    }
}

// ---------------- launch ----------------
extern "C" void kernel_launch(void* const* d_in, const int* in_sizes, int n_in,
                              void* d_out, int out_size) {
    (void)in_sizes; (void)n_in; (void)out_size;
    const float* X      = (const float*)d_in[0];
    const float* dict   = (const float*)d_in[1];
    const float* counts = (const float*)d_in[2];
    float* out = (float*)d_out;

    cudaFuncSetAttribute(gemm_approx,
                         cudaFuncAttributeMaxDynamicSharedMemorySize, SM_TOTAL);

    compute_codewords<<<VOCAB, 128>>>(dict, counts);
    split_e<<<8192, 256>>>();
    split_x<<<32768, 256>>>(X);
    init_kernel<<<2048, 256>>>(dict, out);
    dim3 grid(M_ROWS / TM, VOCAB / TN);   // (256, 32), mt-major
    gemm_approx<<<grid, 512, SM_TOTAL>>>();
    rescore<<<2048, 256>>>(X);
    scatter_kernel<<<M_ROWS * 32 / 256, 256>>>(X, out);
    finalize_kernel<<<1, 1024>>>(counts, out);
}